// round 7
// baseline (speedup 1.0000x reference)
#include <cuda_runtime.h>
#include <cuda_bf16.h>

#define IW 1280
#define IH 720
#define IB 32
#define RPC 4                   // output rows per CTA
#define NYB (IH / RPC)          // 180 row-blocks

#define PADL 68                 // zero floats covering x0 in [-66, -1]
#define ROWF (PADL + IW + 4)    // 1352 floats per h-row buffer

__device__ __forceinline__ float4 loadrow4(const float* __restrict__ imgb,
                                           int row, int xb)
{
    if ((unsigned)row < (unsigned)IH)
        return *reinterpret_cast<const float4*>(imgb + row * IW + xb);
    return make_float4(0.f, 0.f, 0.f, 0.f);
}

__device__ __forceinline__ int y0_of(int y)
{
    float iy = fmaf((float)y, (float)IH / (float)(IH - 1), -0.5f);
    return (int)floorf(iy);
}

__global__ __launch_bounds__(320) void warp_disp_pipe(
    const float* __restrict__ img,
    const float* __restrict__ disp,
    float* __restrict__ out)
{
    __shared__ float sm[2][ROWF];

    const int blk = blockIdx.x;           // = b*NYB + yblk
    const int yb  = (blk % NYB) * RPC;    // first output row of this CTA
    const int b   = blk / NYB;
    const int t   = threadIdx.x;          // 320 threads, 4 px each
    const int xb  = t * 4;

    const float* imgb = img + (size_t)b * (IH * IW);
    const float Ax = (float)IW / (float)(IW - 1);
    const float4 z4 = make_float4(0.f, 0.f, 0.f, 0.f);

    // rolling source rows (registers): s0 = row c0, s1 = row c0+1
    int    c0 = y0_of(yb);
    float4 s0 = loadrow4(imgb, c0,     xb);
    float4 s1 = loadrow4(imgb, c0 + 1, xb);

    int pb = 0;                            // smem ping-pong index
#pragma unroll
    for (int r = 0; r < RPC; r++) {
        const int y = yb + r;

        // vertical weights (uniform per row); (int)floor(iy) == c0 by construction
        float iy  = fmaf((float)y, (float)IH / (float)(IH - 1), -0.5f);
        float y0f = floorf(iy);
        float wy1 = iy - y0f;
        float wy0 = 1.0f - wy1;

        // vertical lerp -> h chunk, one STS.128
        float4 h;
        h.x = fmaf(wy0, s0.x, wy1 * s1.x);
        h.y = fmaf(wy0, s0.y, wy1 * s1.y);
        h.z = fmaf(wy0, s0.z, wy1 * s1.z);
        h.w = fmaf(wy0, s0.w, wy1 * s1.w);

        float* sp = sm[pb] + PADL;
        *reinterpret_cast<float4*>(sp + xb) = h;
        if (r < 2) {                       // pads written once per buffer
            if (t < PADL / 4)
                *reinterpret_cast<float4*>(sm[pb] + t * 4) = z4;
            if (t == 319)
                *reinterpret_cast<float4*>(sp + IW) = z4;
        }

        // prefetch disp for THIS row (consumed after barrier) and the
        // source row(s) for the NEXT row (consumed next iteration).
        const int  p  = (b * IH + y) * IW + xb;
        float4 d4 = *reinterpret_cast<const float4*>(disp + p);

        float4 t0 = s0, t1 = s1;
        int    n0 = c0;
        if (r < RPC - 1) {
            n0 = y0_of(y + 1);             // c0+1 (typ.) or c0+2 (rare)
            if (n0 == c0 + 1) {
                t0 = s1;
                t1 = loadrow4(imgb, n0 + 1, xb);
            } else if (n0 != c0) {
                t0 = loadrow4(imgb, n0,     xb);
                t1 = loadrow4(imgb, n0 + 1, xb);
            }
        }
        __syncthreads();

        // per pixel: 2 scalar LDS + horizontal lerp
        float dv[4] = {d4.x, d4.y, d4.z, d4.w};
        float res[4];
#pragma unroll
        for (int i = 0; i < 4; i++) {
            float u   = (float)(xb + i) - dv[i];
            float ix  = fmaf(u, Ax, -0.5f);
            float x0f = floorf(ix);
            float wx1 = ix - x0f;
            float wx0 = 1.0f - wx1;
            int   x0  = (int)x0f;          // in [-65, 1279]
            float v0 = sp[x0];
            float v1 = sp[x0 + 1];
            res[i] = fmaf(v1, wx1, v0 * wx0);
        }
        *reinterpret_cast<float4*>(out + p) =
            make_float4(res[0], res[1], res[2], res[3]);

        s0 = t0; s1 = t1; c0 = n0;
        pb ^= 1;
    }
}

extern "C" void kernel_launch(void* const* d_in, const int* in_sizes, int n_in,
                              void* d_out, int out_size)
{
    const float* right_img = (const float*)d_in[0];
    const float* disp      = (const float*)d_in[1];
    float*       out       = (float*)d_out;

    const int blocks = IB * NYB;           // 5760 CTAs, 4 rows each
    warp_disp_pipe<<<blocks, 320>>>(right_img, disp, out);
}

// round 8
// speedup vs baseline: 1.0675x; 1.0675x over previous
#include <cuda_runtime.h>
#include <cuda_bf16.h>

#define IW 1280
#define IH 720
#define IB 32

#define SEGW  128               // pixels per warp segment
#define NSEG  (IW / SEGW)       // 10 segments per row
#define HALOL 68                // left halo floats (covers x0 >= xs-65, 16B aligned)
#define WROWF (HALOL + SEGW + 4) // 200 floats per warp buffer (800 B, 16B aligned)
#define WPC   8                 // warps per CTA

__global__ __launch_bounds__(WPC * 32) void warp_disp_ws(
    const float* __restrict__ img,
    const float* __restrict__ disp,
    float* __restrict__ out)
{
    __shared__ float sm[WPC][WROWF];

    const int w    = threadIdx.x >> 5;
    const int lane = threadIdx.x & 31;
    const int seg  = blockIdx.x * WPC + w;      // global segment id
    const int segx = seg % NSEG;
    const int rowi = seg / NSEG;                // = b*IH + y
    const int y    = rowi % IH;
    const int b    = rowi / IH;
    const int xs   = segx * SEGW;

    // ---- vertical terms (uniform per warp): iy = y*H/(H-1) - 0.5 ----
    float iy  = fmaf((float)y, (float)IH / (float)(IH - 1), -0.5f);
    float y0f = floorf(iy);
    float wy1 = iy - y0f;
    float wy0 = 1.0f - wy1;
    int   y0  = (int)y0f;
    int   y1  = y0 + 1;
    bool  vy0 = (unsigned)y0 < (unsigned)IH;
    bool  vy1 = (unsigned)y1 < (unsigned)IH;

    const float* imgb = img + (size_t)b * (IH * IW);
    const float* r0p  = imgb + (vy0 ? y0 : 0) * IW;
    const float* r1p  = imgb + (vy1 ? y1 : 0) * IW;

    // disp prefetch (consumed after gather setup)
    const int p = rowi * IW + xs + lane * 4;
    float4 d4 = *reinterpret_cast<const float4*>(disp + p);

    // ---- stage h-window: slots cover x in [xs-68, xs+132), 50 float4 slots ----
    float* smw = sm[w];
    const float4 z4 = make_float4(0.f, 0.f, 0.f, 0.f);

#pragma unroll
    for (int ld = 0; ld < 2; ld++) {
        int s = lane + ld * 32;
        if (ld == 0 || lane < (WROWF / 4 - 32)) {     // slots 0..49
            int gx = xs - HALOL + s * 4;              // multiple of 4
            bool vx = (unsigned)gx < (unsigned)IW;    // fully in iff gx in [0,1276]
            float4 a0 = (vx && vy0) ? *reinterpret_cast<const float4*>(r0p + gx) : z4;
            float4 a1 = (vx && vy1) ? *reinterpret_cast<const float4*>(r1p + gx) : z4;
            float4 h;
            h.x = fmaf(wy0, a0.x, wy1 * a1.x);
            h.y = fmaf(wy0, a0.y, wy1 * a1.y);
            h.z = fmaf(wy0, a0.z, wy1 * a1.z);
            h.w = fmaf(wy0, a0.w, wy1 * a1.w);
            *reinterpret_cast<float4*>(smw + s * 4) = h;
        }
    }
    __syncwarp();

    // ---- per pixel: 2 scalar LDS + horizontal lerp (4 px per lane) ----
    const float Ax = (float)IW / (float)(IW - 1);
    const float* sp = smw + HALOL;                    // sp[x0 - xs] valid for x0 in [xs-65, xs+128]
    float dv[4] = {d4.x, d4.y, d4.z, d4.w};
    float res[4];
    const int xb = xs + lane * 4;

#pragma unroll
    for (int i = 0; i < 4; i++) {
        float u   = (float)(xb + i) - dv[i];
        float ix  = fmaf(u, Ax, -0.5f);
        float x0f = floorf(ix);
        float wx1 = ix - x0f;
        float wx0 = 1.0f - wx1;
        int   xr  = (int)x0f - xs;                    // in [-65, 128]
        float v0 = sp[xr];
        float v1 = sp[xr + 1];
        res[i] = fmaf(v1, wx1, v0 * wx0);
    }

    *reinterpret_cast<float4*>(out + p) = make_float4(res[0], res[1], res[2], res[3]);
}

extern "C" void kernel_launch(void* const* d_in, const int* in_sizes, int n_in,
                              void* d_out, int out_size)
{
    const float* right_img = (const float*)d_in[0];
    const float* disp      = (const float*)d_in[1];
    float*       out       = (float*)d_out;

    const int nseg   = IB * IH * NSEG;        // 230400 warp segments
    const int blocks = nseg / WPC;            // 28800 CTAs of 8 warps
    warp_disp_ws<<<blocks, WPC * 32>>>(right_img, disp, out);
}